// round 1
// baseline (speedup 1.0000x reference)
#include <cuda_runtime.h>
#include <cuda_bf16.h>

#define B_    8192
#define F_    256
#define HALF_ 128
#define H_    512
#define K_    32768
#define L_    4
#define NSPLIT 8
#define KC    (K_ / NSPLIT)   // codes per split = 4096

// ---------------- scratch (no allocations allowed) ----------------
__device__ float g_xA[B_ * F_];
__device__ float g_xB[B_ * F_];
__device__ float g_H[B_ * H_];
__device__ float g_jac[B_];
__device__ float g_nb[K_];
__device__ float g_pmin[B_ * NSPLIT];
__device__ int   g_pidx[B_ * NSPLIT];
__device__ float g_partial[B_ / 8];

// ---------------- ||prior_k||^2 ----------------
__global__ __launch_bounds__(256) void nb_kernel(const float* __restrict__ prior) {
    int k = blockIdx.x * 256 + threadIdx.x;
    const float4* p = (const float4*)(prior + (size_t)k * F_);
    float s = 0.f;
#pragma unroll
    for (int i = 0; i < F_ / 4; i++) {
        float4 v = p[i];
        s = fmaf(v.x, v.x, s); s = fmaf(v.y, v.y, s);
        s = fmaf(v.z, v.z, s); s = fmaf(v.w, v.w, s);
    }
    g_nb[k] = s;
}

// ---------------- H = relu(xa @ W1 + b1) : [8192,128]x[128,512] ----------------
// block tile 128x128, 256 threads, 8x8 per thread
__global__ __launch_bounds__(256) void hidden_kernel(
    const float* __restrict__ xin, const float* __restrict__ W1,
    const float* __restrict__ b1, float* __restrict__ Hout)
{
    __shared__ __align__(16) float As[16][132];
    __shared__ __align__(16) float Bs[16][132];
    int tid = threadIdx.x;
    int ty = tid >> 4, tx = tid & 15;
    int rowbase = blockIdx.x * 128;
    int nbase   = blockIdx.y * 128;
    float acc[8][8] = {};

    for (int k0 = 0; k0 < HALF_; k0 += 16) {
#pragma unroll
        for (int i = 0; i < 8; i++) {
            int e = tid + i * 256;
            int m = e >> 4, kk = e & 15;
            As[kk][m] = xin[(size_t)(rowbase + m) * F_ + k0 + kk];
        }
#pragma unroll
        for (int i = 0; i < 8; i++) {
            int e = tid + i * 256;
            int kk = e >> 7, n = e & 127;
            Bs[kk][n] = W1[(size_t)(k0 + kk) * H_ + nbase + n];
        }
        __syncthreads();
#pragma unroll
        for (int kk = 0; kk < 16; kk++) {
            float4 a0 = *(const float4*)&As[kk][ty * 8];
            float4 a1 = *(const float4*)&As[kk][ty * 8 + 4];
            float4 b0 = *(const float4*)&Bs[kk][tx * 8];
            float4 b1 = *(const float4*)&Bs[kk][tx * 8 + 4];
            float a[8] = {a0.x, a0.y, a0.z, a0.w, a1.x, a1.y, a1.z, a1.w};
            float b[8] = {b0.x, b0.y, b0.z, b0.w, b1.x, b1.y, b1.z, b1.w};
#pragma unroll
            for (int i = 0; i < 8; i++)
#pragma unroll
                for (int j = 0; j < 8; j++)
                    acc[i][j] = fmaf(a[i], b[j], acc[i][j]);
        }
        __syncthreads();
    }
#pragma unroll
    for (int i = 0; i < 8; i++) {
        int r = rowbase + ty * 8 + i;
#pragma unroll
        for (int j = 0; j < 8; j++) {
            int c = nbase + tx * 8 + j;
            float v = acc[i][j] + b1[c];
            Hout[(size_t)r * H_ + c] = v > 0.f ? v : 0.f;
        }
    }
}

// ---------------- s,t = H@Ws+bs , H@Wt+bt ; coupling epilogue ----------------
// block tile 64x128 (full N), 256 threads, 4x8 per thread per output
__global__ __launch_bounds__(256) void st_kernel(
    const float* __restrict__ xin, const float* __restrict__ Hin,
    const float* __restrict__ Ws, const float* __restrict__ bs,
    const float* __restrict__ Wt, const float* __restrict__ bt,
    float* __restrict__ xout, int is_last, int accum_jac)
{
    __shared__ __align__(16) float As[16][68];
    __shared__ __align__(16) float Bss[16][132];
    __shared__ __align__(16) float Bst[16][132];
    __shared__ float red[64 * 16];
    int tid = threadIdx.x;
    int ty = tid >> 4, tx = tid & 15;
    int rowbase = blockIdx.x * 64;
    float accs[4][8] = {};
    float acct[4][8] = {};

    for (int k0 = 0; k0 < H_; k0 += 16) {
#pragma unroll
        for (int i = 0; i < 4; i++) {
            int e = tid + i * 256;
            int m = e >> 4, kk = e & 15;
            As[kk][m] = Hin[(size_t)(rowbase + m) * H_ + k0 + kk];
        }
#pragma unroll
        for (int i = 0; i < 8; i++) {
            int e = tid + i * 256;
            int kk = e >> 7, n = e & 127;
            Bss[kk][n] = Ws[(size_t)(k0 + kk) * HALF_ + n];
            Bst[kk][n] = Wt[(size_t)(k0 + kk) * HALF_ + n];
        }
        __syncthreads();
#pragma unroll
        for (int kk = 0; kk < 16; kk++) {
            float a[4];
#pragma unroll
            for (int i = 0; i < 4; i++) a[i] = As[kk][ty * 4 + i];
            float4 b0 = *(const float4*)&Bss[kk][tx * 8];
            float4 b1 = *(const float4*)&Bss[kk][tx * 8 + 4];
            float4 c0 = *(const float4*)&Bst[kk][tx * 8];
            float4 c1 = *(const float4*)&Bst[kk][tx * 8 + 4];
            float bb[8] = {b0.x, b0.y, b0.z, b0.w, b1.x, b1.y, b1.z, b1.w};
            float cc[8] = {c0.x, c0.y, c0.z, c0.w, c1.x, c1.y, c1.z, c1.w};
#pragma unroll
            for (int i = 0; i < 4; i++)
#pragma unroll
                for (int j = 0; j < 8; j++) {
                    accs[i][j] = fmaf(a[i], bb[j], accs[i][j]);
                    acct[i][j] = fmaf(a[i], cc[j], acct[i][j]);
                }
        }
        __syncthreads();
    }

    float ssum[4] = {0.f, 0.f, 0.f, 0.f};
#pragma unroll
    for (int i = 0; i < 4; i++) {
        int r = rowbase + ty * 4 + i;
#pragma unroll
        for (int j = 0; j < 8; j++) {
            int c = tx * 8 + j;
            float sr = accs[i][j] + bs[c];
            float sa = is_last ? sr : tanhf(sr);
            float tv = acct[i][j] + bt[c];
            float xa = xin[(size_t)r * F_ + c];
            float xb = xin[(size_t)r * F_ + HALF_ + c];
            xout[(size_t)r * F_ + c]         = fmaf(xb, expf(sa), tv);
            xout[(size_t)r * F_ + HALF_ + c] = xa;
            ssum[i] += sa;
        }
    }
#pragma unroll
    for (int i = 0; i < 4; i++) red[(ty * 4 + i) * 16 + tx] = ssum[i];
    __syncthreads();
    if (tid < 64) {
        float s = 0.f;
#pragma unroll
        for (int q = 0; q < 16; q++) s += red[tid * 16 + q];
        int r = rowbase + tid;
        if (accum_jac) g_jac[r] += s; else g_jac[r] = s;
    }
}

// ---------------- fused distance GEMM + argmin (split over codebook) ----------------
// grid (64, NSPLIT). block: 128 rows x 128-code tiles, 256 threads, 8x8/thread
__global__ __launch_bounds__(256) void argmin_kernel(
    const float* __restrict__ x, const float* __restrict__ prior)
{
    __shared__ __align__(16) float As[16][132];
    __shared__ __align__(16) float Ps[16][132];
    __shared__ float redv[128 * 16];
    __shared__ int   redi[128 * 16];
    int tid = threadIdx.x;
    int ty = tid >> 4, tx = tid & 15;
    int rowbase = blockIdx.x * 128;
    int split = blockIdx.y;

    float minv[8];
    int   mini[8];
#pragma unroll
    for (int i = 0; i < 8; i++) { minv[i] = 3.4e38f; mini[i] = 0; }

    for (int ct = 0; ct < KC / 128; ct++) {
        int codebase = split * KC + ct * 128;
        float acc[8][8] = {};
        for (int k0 = 0; k0 < F_; k0 += 16) {
#pragma unroll
            for (int i = 0; i < 8; i++) {
                int e = tid + i * 256;
                int m = e >> 4, kk = e & 15;
                As[kk][m] = x[(size_t)(rowbase + m) * F_ + k0 + kk];
            }
#pragma unroll
            for (int i = 0; i < 8; i++) {
                int e = tid + i * 256;
                int n = e >> 4, kk = e & 15;
                Ps[kk][n] = prior[(size_t)(codebase + n) * F_ + k0 + kk];
            }
            __syncthreads();
#pragma unroll
            for (int kk = 0; kk < 16; kk++) {
                float4 a0 = *(const float4*)&As[kk][ty * 8];
                float4 a1 = *(const float4*)&As[kk][ty * 8 + 4];
                float4 b0 = *(const float4*)&Ps[kk][tx * 8];
                float4 b1 = *(const float4*)&Ps[kk][tx * 8 + 4];
                float a[8] = {a0.x, a0.y, a0.z, a0.w, a1.x, a1.y, a1.z, a1.w};
                float b[8] = {b0.x, b0.y, b0.z, b0.w, b1.x, b1.y, b1.z, b1.w};
#pragma unroll
                for (int i = 0; i < 8; i++)
#pragma unroll
                    for (int j = 0; j < 8; j++)
                        acc[i][j] = fmaf(a[i], b[j], acc[i][j]);
            }
            __syncthreads();
        }
        // argmin over d' = ||p||^2 - 2 x.p  (||x||^2 constant per row; no clamp hits: d>>0)
#pragma unroll
        for (int j = 0; j < 8; j++) {
            int code = codebase + tx * 8 + j;     // ascending scan -> first-min tie rule
            float nb = g_nb[code];
#pragma unroll
            for (int i = 0; i < 8; i++) {
                float v = fmaf(-2.f, acc[i][j], nb);
                if (v < minv[i]) { minv[i] = v; mini[i] = code; }
            }
        }
    }
#pragma unroll
    for (int i = 0; i < 8; i++) {
        redv[(ty * 8 + i) * 16 + tx] = minv[i];
        redi[(ty * 8 + i) * 16 + tx] = mini[i];
    }
    __syncthreads();
    if (tid < 128) {
        float bv = redv[tid * 16]; int bi = redi[tid * 16];
#pragma unroll
        for (int q = 1; q < 16; q++) {
            float v = redv[tid * 16 + q]; int ii = redi[tid * 16 + q];
            if (v < bv || (v == bv && ii < bi)) { bv = v; bi = ii; }
        }
        g_pmin[(size_t)(rowbase + tid) * NSPLIT + split] = bv;
        g_pidx[(size_t)(rowbase + tid) * NSPLIT + split] = bi;
    }
}

// ---------------- per-row loss partials (deterministic, no float atomics) ----------------
__global__ __launch_bounds__(256) void loss_kernel(
    const float* __restrict__ x, const float* __restrict__ prior)
{
    int warp = threadIdx.x >> 5, lane = threadIdx.x & 31;
    int r = blockIdx.x * 8 + warp;
    float v = 3.4e38f; int idx = 0x7fffffff;
    if (lane < NSPLIT) { v = g_pmin[(size_t)r * NSPLIT + lane]; idx = g_pidx[(size_t)r * NSPLIT + lane]; }
#pragma unroll
    for (int off = 4; off; off >>= 1) {
        float ov = __shfl_down_sync(0xffffffff, v, off);
        int   oi = __shfl_down_sync(0xffffffff, idx, off);
        if (ov < v || (ov == v && oi < idx)) { v = ov; idx = oi; }
    }
    idx = __shfl_sync(0xffffffff, idx, 0);
    float ss = 0.f;
#pragma unroll
    for (int f = lane; f < F_; f += 32) {
        float d = x[(size_t)r * F_ + f] - prior[(size_t)idx * F_ + f];
        ss = fmaf(d, d, ss);
    }
#pragma unroll
    for (int off = 16; off; off >>= 1) ss += __shfl_down_sync(0xffffffff, ss, off);
    __shared__ float part[8];
    if (lane == 0) part[warp] = fmaf(0.625f, ss, -g_jac[r]);  // loss1+0.25*loss2 = 1.25*ss/2
    __syncthreads();
    if (threadIdx.x == 0) {
        float s = 0.f;
#pragma unroll
        for (int i = 0; i < 8; i++) s += part[i];
        g_partial[blockIdx.x] = s;
    }
}

__global__ __launch_bounds__(256) void final_kernel(float* out, int out_size) {
    __shared__ float sm[256];
    int tid = threadIdx.x;
    float s = 0.f;
    for (int i = tid; i < B_ / 8; i += 256) s += g_partial[i];  // fixed order: deterministic
    sm[tid] = s;
    __syncthreads();
    for (int st = 128; st; st >>= 1) { if (tid < st) sm[tid] += sm[tid + st]; __syncthreads(); }
    float loss = sm[0] / (float)B_;
    for (int i = B_ * F_ + tid; i < out_size; i += 256) out[i] = loss;
}

// ---------------- launch ----------------
extern "C" void kernel_launch(void* const* d_in, const int* in_sizes, int n_in,
                              void* d_out, int out_size) {
    const float* x0    = (const float*)d_in[0];
    const float* W1    = (const float*)d_in[1];
    const float* b1    = (const float*)d_in[2];
    const float* Ws    = (const float*)d_in[3];
    const float* bs    = (const float*)d_in[4];
    const float* Wt    = (const float*)d_in[5];
    const float* bt    = (const float*)d_in[6];
    const float* prior = (const float*)d_in[7];
    float* out = (float*)d_out;

    void *pA, *pB, *pH;
    cudaGetSymbolAddress(&pA, g_xA);
    cudaGetSymbolAddress(&pB, g_xB);
    cudaGetSymbolAddress(&pH, g_H);
    float* gxA = (float*)pA;
    float* gxB = (float*)pB;
    float* gH  = (float*)pH;

    nb_kernel<<<K_ / 256, 256>>>(prior);

    const float* cur = x0;
    float* bufs[2] = { gxA, gxB };
    for (int l = 0; l < L_; l++) {
        hidden_kernel<<<dim3(B_ / 128, H_ / 128), 256>>>(
            cur, W1 + (size_t)l * HALF_ * H_, b1 + (size_t)l * H_, gH);
        float* xout = (l == L_ - 1) ? out : bufs[l & 1];
        st_kernel<<<B_ / 64, 256>>>(
            cur, gH,
            Ws + (size_t)l * H_ * HALF_, bs + (size_t)l * HALF_,
            Wt + (size_t)l * H_ * HALF_, bt + (size_t)l * HALF_,
            xout, (l == L_ - 1) ? 1 : 0, (l > 0) ? 1 : 0);
        cur = xout;
    }

    argmin_kernel<<<dim3(B_ / 128, NSPLIT), 256>>>(out, prior);
    loss_kernel<<<B_ / 8, 256>>>(out, prior);
    if (out_size > B_ * F_)
        final_kernel<<<1, 256>>>(out, out_size);
}

// round 3
// speedup vs baseline: 4.2646x; 4.2646x over previous
#include <cuda_runtime.h>
#include <cuda_bf16.h>
#include <cstdint>

#define B_    8192
#define F_    256
#define HALF_ 128
#define H_    512
#define K_    32768
#define L_    4
#define NSPLIT 16
#define TM 128
#define TN 128
#define TK 256
#define NT (K_ / NSPLIT / TN)   // 16 code tiles per CTA

#define STRB 528                // bytes per smem tile row (264 bf16: 256 data + 8 pad)
#define TILE_BYTES (128 * STRB) // 67584

// ---------------- scratch (no allocations allowed) ----------------
__device__ float g_xA[B_ * F_];
__device__ float g_xB[B_ * F_];
__device__ float g_H[B_ * H_];
__device__ float g_jac[B_];
__device__ float g_nb[K_];
__device__ float g_pmin[B_ * NSPLIT];
__device__ int   g_pidx[B_ * NSPLIT];
__device__ float g_partial[B_ / 8];
__device__ __nv_bfloat16 g_pb[K_ * F_];
__device__ __nv_bfloat16 g_xb[B_ * F_];

// ============ PTX helpers (compute_103-safe: sm_80-era tensor ops) ============
__device__ __forceinline__ uint32_t smem_to_u32(const void* p) {
    uint32_t a;
    asm("{ .reg .u64 t; cvta.to.shared.u64 t, %1; cvt.u32.u64 %0, t; }" : "=r"(a) : "l"(p));
    return a;
}
__device__ __forceinline__ void cp16(uint32_t dst, const void* src) {
    asm volatile("cp.async.cg.shared.global [%0], [%1], 16;" :: "r"(dst), "l"(src));
}
#define CP_COMMIT() asm volatile("cp.async.commit_group;" ::: "memory")
#define CP_WAIT0()  asm volatile("cp.async.wait_group 0;" ::: "memory")

__device__ __forceinline__ void ldm_x4(uint32_t* r, uint32_t a) {
    asm volatile("ldmatrix.sync.aligned.m8n8.x4.shared.b16 {%0,%1,%2,%3}, [%4];"
        : "=r"(r[0]), "=r"(r[1]), "=r"(r[2]), "=r"(r[3]) : "r"(a));
}
__device__ __forceinline__ void mma_bf16(float* c, const uint32_t* a, const uint32_t* b) {
    asm volatile(
        "mma.sync.aligned.m16n8k16.row.col.f32.bf16.bf16.f32 "
        "{%0,%1,%2,%3}, {%4,%5,%6,%7}, {%8,%9}, {%0,%1,%2,%3};"
        : "+f"(c[0]), "+f"(c[1]), "+f"(c[2]), "+f"(c[3])
        : "r"(a[0]), "r"(a[1]), "r"(a[2]), "r"(a[3]), "r"(b[0]), "r"(b[1]));
}

// ---------------- fp32 -> bf16 conversion ----------------
__global__ __launch_bounds__(256) void cvt_bf16_kernel(
    const float* __restrict__ src, __nv_bfloat16* __restrict__ dst) {
    int i = blockIdx.x * 256 + threadIdx.x;
    float4 v = ((const float4*)src)[i];
    __nv_bfloat162 lo = __floats2bfloat162_rn(v.x, v.y);
    __nv_bfloat162 hi = __floats2bfloat162_rn(v.z, v.w);
    uint2 u;
    u.x = *(uint32_t*)&lo; u.y = *(uint32_t*)&hi;
    ((uint2*)dst)[i] = u;
}

// ---------------- ||prior_k||^2 ----------------
__global__ __launch_bounds__(256) void nb_kernel(const float* __restrict__ prior) {
    int k = blockIdx.x * 256 + threadIdx.x;
    const float4* p = (const float4*)(prior + (size_t)k * F_);
    float s = 0.f;
#pragma unroll
    for (int i = 0; i < F_ / 4; i++) {
        float4 v = p[i];
        s = fmaf(v.x, v.x, s); s = fmaf(v.y, v.y, s);
        s = fmaf(v.z, v.z, s); s = fmaf(v.w, v.w, s);
    }
    g_nb[k] = s;
}

// ---------------- H = relu(xa @ W1 + b1) (unchanged) ----------------
__global__ __launch_bounds__(256) void hidden_kernel(
    const float* __restrict__ xin, const float* __restrict__ W1,
    const float* __restrict__ b1, float* __restrict__ Hout)
{
    __shared__ __align__(16) float As[16][132];
    __shared__ __align__(16) float Bs[16][132];
    int tid = threadIdx.x;
    int ty = tid >> 4, tx = tid & 15;
    int rowbase = blockIdx.x * 128;
    int nbase   = blockIdx.y * 128;
    float acc[8][8] = {};

    for (int k0 = 0; k0 < HALF_; k0 += 16) {
#pragma unroll
        for (int i = 0; i < 8; i++) {
            int e = tid + i * 256;
            int m = e >> 4, kk = e & 15;
            As[kk][m] = xin[(size_t)(rowbase + m) * F_ + k0 + kk];
        }
#pragma unroll
        for (int i = 0; i < 8; i++) {
            int e = tid + i * 256;
            int kk = e >> 7, n = e & 127;
            Bs[kk][n] = W1[(size_t)(k0 + kk) * H_ + nbase + n];
        }
        __syncthreads();
#pragma unroll
        for (int kk = 0; kk < 16; kk++) {
            float4 a0 = *(const float4*)&As[kk][ty * 8];
            float4 a1 = *(const float4*)&As[kk][ty * 8 + 4];
            float4 b0 = *(const float4*)&Bs[kk][tx * 8];
            float4 b1 = *(const float4*)&Bs[kk][tx * 8 + 4];
            float a[8] = {a0.x, a0.y, a0.z, a0.w, a1.x, a1.y, a1.z, a1.w};
            float b[8] = {b0.x, b0.y, b0.z, b0.w, b1.x, b1.y, b1.z, b1.w};
#pragma unroll
            for (int i = 0; i < 8; i++)
#pragma unroll
                for (int j = 0; j < 8; j++)
                    acc[i][j] = fmaf(a[i], b[j], acc[i][j]);
        }
        __syncthreads();
    }
#pragma unroll
    for (int i = 0; i < 8; i++) {
        int r = rowbase + ty * 8 + i;
#pragma unroll
        for (int j = 0; j < 8; j++) {
            int c = nbase + tx * 8 + j;
            float v = acc[i][j] + b1[c];
            Hout[(size_t)r * H_ + c] = v > 0.f ? v : 0.f;
        }
    }
}

// ---------------- s,t GEMMs + coupling epilogue (unchanged) ----------------
__global__ __launch_bounds__(256) void st_kernel(
    const float* __restrict__ xin, const float* __restrict__ Hin,
    const float* __restrict__ Ws, const float* __restrict__ bs,
    const float* __restrict__ Wt, const float* __restrict__ bt,
    float* __restrict__ xout, int is_last, int accum_jac)
{
    __shared__ __align__(16) float As[16][68];
    __shared__ __align__(16) float Bss[16][132];
    __shared__ __align__(16) float Bst[16][132];
    __shared__ float red[64 * 16];
    int tid = threadIdx.x;
    int ty = tid >> 4, tx = tid & 15;
    int rowbase = blockIdx.x * 64;
    float accs[4][8] = {};
    float acct[4][8] = {};

    for (int k0 = 0; k0 < H_; k0 += 16) {
#pragma unroll
        for (int i = 0; i < 4; i++) {
            int e = tid + i * 256;
            int m = e >> 4, kk = e & 15;
            As[kk][m] = Hin[(size_t)(rowbase + m) * H_ + k0 + kk];
        }
#pragma unroll
        for (int i = 0; i < 8; i++) {
            int e = tid + i * 256;
            int kk = e >> 7, n = e & 127;
            Bss[kk][n] = Ws[(size_t)(k0 + kk) * HALF_ + n];
            Bst[kk][n] = Wt[(size_t)(k0 + kk) * HALF_ + n];
        }
        __syncthreads();
#pragma unroll
        for (int kk = 0; kk < 16; kk++) {
            float a[4];
#pragma unroll
            for (int i = 0; i < 4; i++) a[i] = As[kk][ty * 4 + i];
            float4 b0 = *(const float4*)&Bss[kk][tx * 8];
            float4 b1 = *(const float4*)&Bss[kk][tx * 8 + 4];
            float4 c0 = *(const float4*)&Bst[kk][tx * 8];
            float4 c1 = *(const float4*)&Bst[kk][tx * 8 + 4];
            float bb[8] = {b0.x, b0.y, b0.z, b0.w, b1.x, b1.y, b1.z, b1.w};
            float cc[8] = {c0.x, c0.y, c0.z, c0.w, c1.x, c1.y, c1.z, c1.w};
#pragma unroll
            for (int i = 0; i < 4; i++)
#pragma unroll
                for (int j = 0; j < 8; j++) {
                    accs[i][j] = fmaf(a[i], bb[j], accs[i][j]);
                    acct[i][j] = fmaf(a[i], cc[j], acct[i][j]);
                }
        }
        __syncthreads();
    }

    float ssum[4] = {0.f, 0.f, 0.f, 0.f};
#pragma unroll
    for (int i = 0; i < 4; i++) {
        int r = rowbase + ty * 4 + i;
#pragma unroll
        for (int j = 0; j < 8; j++) {
            int c = tx * 8 + j;
            float sr = accs[i][j] + bs[c];
            float sa = is_last ? sr : tanhf(sr);
            float tv = acct[i][j] + bt[c];
            float xa = xin[(size_t)r * F_ + c];
            float xb = xin[(size_t)r * F_ + HALF_ + c];
            xout[(size_t)r * F_ + c]         = fmaf(xb, expf(sa), tv);
            xout[(size_t)r * F_ + HALF_ + c] = xa;
            ssum[i] += sa;
        }
    }
#pragma unroll
    for (int i = 0; i < 4; i++) red[(ty * 4 + i) * 16 + tx] = ssum[i];
    __syncthreads();
    if (tid < 64) {
        float s = 0.f;
#pragma unroll
        for (int q = 0; q < 16; q++) s += red[tid * 16 + q];
        int r = rowbase + tid;
        if (accum_jac) g_jac[r] += s; else g_jac[r] = s;
    }
}

// ---------------- mma.sync bf16 distance GEMM + fused argmin ----------------
// grid (64, NSPLIT), 256 threads (8 warps, 2x4). CTA tile 128 rows x 128 codes, K=256.
__global__ __launch_bounds__(256, 1) void argmin_mma_kernel(
    const __nv_bfloat16* __restrict__ xb, const __nv_bfloat16* __restrict__ pb)
{
    extern __shared__ char dsmem[];
    __shared__ __align__(16) float s_nb[2][TN];
    __shared__ float redv[TM][4];
    __shared__ int   redi[TM][4];

    char* Aptr  = dsmem;
    char* Bptr[2] = { dsmem + TILE_BYTES, dsmem + 2 * TILE_BYTES };
    uint32_t Abase = smem_to_u32(Aptr);
    uint32_t Bbase[2] = { Abase + TILE_BYTES, Abase + 2 * TILE_BYTES };

    int tid = threadIdx.x;
    int wid = tid >> 5, lane = tid & 31;
    int warp_m = wid & 1;        // 0..1 -> 64-row half
    int warp_n = wid >> 1;       // 0..3 -> 32-code slice
    int rowbase = blockIdx.x * TM;
    int split = blockIdx.y;
    int code0 = split * (K_ / NSPLIT);

    // ---- prologue: stage A (all 128 rows x 256 k) and B tile 0 via cp.async ----
#pragma unroll
    for (int i = 0; i < 16; i++) {
        int e = tid + i * 256;
        int r = e >> 5, c = e & 31;                    // 32 x 16B chunks per row
        cp16(Abase + r * STRB + c * 16,
             (const char*)(xb + (size_t)(rowbase + r) * TK) + c * 16);
    }
#pragma unroll
    for (int i = 0; i < 16; i++) {
        int e = tid + i * 256;
        int r = e >> 5, c = e & 31;
        cp16(Bbase[0] + r * STRB + c * 16,
             (const char*)(pb + (size_t)(code0 + r) * TK) + c * 16);
    }
    if (tid < TN) s_nb[0][tid] = g_nb[code0 + tid];
    CP_COMMIT();
    CP_WAIT0();
    __syncthreads();

    // ldmatrix base offsets (byte offsets inside a tile)
    // A frag (m16k16): row = warp_m*64 + mi*16 + (lane&15), col8 = (lane>>4)*8
    uint32_t aoff = (uint32_t)((warp_m * 64 + (lane & 15)) * STRB + ((lane >> 4) * 8) * 2);
    // B frag pair (two n8k16): row = warp_n*32 + pair*16 + ((lane>>4)&1)*8 + (lane&7)
    //                          col8 = ((lane>>3)&1)*8
    uint32_t boff = (uint32_t)((warp_n * 32 + ((lane >> 4) & 1) * 8 + (lane & 7)) * STRB
                               + (((lane >> 3) & 1) * 8) * 2);

    float minv[8];
    int   mini[8];
#pragma unroll
    for (int i = 0; i < 8; i++) { minv[i] = 3.4e38f; mini[i] = 0; }

    for (int t = 0; t < NT; t++) {
        int cb = t & 1;
        // prefetch next B tile + its ||p||^2 row
        if (t + 1 < NT) {
            int nb_ = (t + 1) & 1;
            int codeN = code0 + (t + 1) * TN;
#pragma unroll
            for (int i = 0; i < 16; i++) {
                int e = tid + i * 256;
                int r = e >> 5, c = e & 31;
                cp16(Bbase[nb_] + r * STRB + c * 16,
                     (const char*)(pb + (size_t)(codeN + r) * TK) + c * 16);
            }
            CP_COMMIT();
            if (tid < TN) s_nb[nb_][tid] = g_nb[codeN + tid];
        }

        // ---- compute tile t ----
        float acc[4][4][4];
#pragma unroll
        for (int mi = 0; mi < 4; mi++)
#pragma unroll
            for (int ni = 0; ni < 4; ni++)
#pragma unroll
                for (int q = 0; q < 4; q++) acc[mi][ni][q] = 0.f;

#pragma unroll
        for (int kc = 0; kc < 16; kc++) {
            uint32_t kb = kc * 32;  // 16 bf16 = 32 bytes
            uint32_t afrag[4][4], bfrag[4][2];
#pragma unroll
            for (int mi = 0; mi < 4; mi++)
                ldm_x4(afrag[mi], Abase + aoff + kb + (uint32_t)(mi * 16 * STRB));
#pragma unroll
            for (int pr = 0; pr < 2; pr++) {
                uint32_t r4[4];
                ldm_x4(r4, Bbase[cb] + boff + kb + (uint32_t)(pr * 16 * STRB));
                bfrag[pr * 2 + 0][0] = r4[0]; bfrag[pr * 2 + 0][1] = r4[1];
                bfrag[pr * 2 + 1][0] = r4[2]; bfrag[pr * 2 + 1][1] = r4[3];
            }
#pragma unroll
            for (int mi = 0; mi < 4; mi++)
#pragma unroll
                for (int ni = 0; ni < 4; ni++)
                    mma_bf16(acc[mi][ni], afrag[mi], bfrag[ni]);
        }

        // ---- fused epilogue: v = ||p||^2 - 2*dot, per-thread argmin ----
        int ctile = code0 + t * TN;
#pragma unroll
        for (int mi = 0; mi < 4; mi++)
#pragma unroll
            for (int ni = 0; ni < 4; ni++)
#pragma unroll
                for (int q = 0; q < 4; q++) {
                    int cl = warp_n * 32 + ni * 8 + (lane & 3) * 2 + (q & 1);
                    float v = fmaf(-2.f, acc[mi][ni][q], s_nb[cb][cl]);
                    int ridx = mi * 2 + (q >> 1);
                    if (v < minv[ridx]) { minv[ridx] = v; mini[ridx] = ctile + cl; }
                }

        CP_WAIT0();
        __syncthreads();
    }

    // ---- reduce across the 4 lanes of each row group (lane&3) ----
#pragma unroll
    for (int ridx = 0; ridx < 8; ridx++) {
        float v = minv[ridx]; int ii = mini[ridx];
#pragma unroll
        for (int off = 1; off <= 2; off <<= 1) {
            float ov = __shfl_xor_sync(0xffffffff, v, off);
            int   oi = __shfl_xor_sync(0xffffffff, ii, off);
            if (ov < v || (ov == v && oi < ii)) { v = ov; ii = oi; }
        }
        if ((lane & 3) == 0) {
            int row = warp_m * 64 + (ridx >> 1) * 16 + (ridx & 1) * 8 + (lane >> 2);
            redv[row][warp_n] = v;
            redi[row][warp_n] = ii;
        }
    }
    __syncthreads();
    if (tid < TM) {
        float bv = redv[tid][0]; int bi = redi[tid][0];
#pragma unroll
        for (int q = 1; q < 4; q++) {
            float v = redv[tid][q]; int ii = redi[tid][q];
            if (v < bv || (v == bv && ii < bi)) { bv = v; bi = ii; }
        }
        g_pmin[(size_t)(rowbase + tid) * NSPLIT + split] = bv;
        g_pidx[(size_t)(rowbase + tid) * NSPLIT + split] = bi;
    }
}

// ---------------- per-row loss partials (deterministic) ----------------
__global__ __launch_bounds__(256) void loss_kernel(
    const float* __restrict__ x, const float* __restrict__ prior)
{
    int warp = threadIdx.x >> 5, lane = threadIdx.x & 31;
    int r = blockIdx.x * 8 + warp;
    float v = 3.4e38f; int idx = 0x7fffffff;
    if (lane < NSPLIT) { v = g_pmin[(size_t)r * NSPLIT + lane]; idx = g_pidx[(size_t)r * NSPLIT + lane]; }
#pragma unroll
    for (int off = 8; off; off >>= 1) {
        float ov = __shfl_down_sync(0xffffffff, v, off);
        int   oi = __shfl_down_sync(0xffffffff, idx, off);
        if (ov < v || (ov == v && oi < idx)) { v = ov; idx = oi; }
    }
    idx = __shfl_sync(0xffffffff, idx, 0);
    float ss = 0.f;
#pragma unroll
    for (int f = lane; f < F_; f += 32) {
        float d = x[(size_t)r * F_ + f] - prior[(size_t)idx * F_ + f];
        ss = fmaf(d, d, ss);
    }
#pragma unroll
    for (int off = 16; off; off >>= 1) ss += __shfl_down_sync(0xffffffff, ss, off);
    __shared__ float part[8];
    if (lane == 0) part[warp] = fmaf(0.625f, ss, -g_jac[r]);
    __syncthreads();
    if (threadIdx.x == 0) {
        float s = 0.f;
#pragma unroll
        for (int i = 0; i < 8; i++) s += part[i];
        g_partial[blockIdx.x] = s;
    }
}

__global__ __launch_bounds__(256) void final_kernel(float* out, int out_size) {
    __shared__ float sm[256];
    int tid = threadIdx.x;
    float s = 0.f;
    for (int i = tid; i < B_ / 8; i += 256) s += g_partial[i];
    sm[tid] = s;
    __syncthreads();
    for (int st = 128; st; st >>= 1) { if (tid < st) sm[tid] += sm[tid + st]; __syncthreads(); }
    float loss = sm[0] / (float)B_;
    for (int i = B_ * F_ + tid; i < out_size; i += 256) out[i] = loss;
}

// ---------------- launch ----------------
extern "C" void kernel_launch(void* const* d_in, const int* in_sizes, int n_in,
                              void* d_out, int out_size) {
    const float* x0    = (const float*)d_in[0];
    const float* W1    = (const float*)d_in[1];
    const float* b1    = (const float*)d_in[2];
    const float* Ws    = (const float*)d_in[3];
    const float* bs    = (const float*)d_in[4];
    const float* Wt    = (const float*)d_in[5];
    const float* bt    = (const float*)d_in[6];
    const float* prior = (const float*)d_in[7];
    float* out = (float*)d_out;

    void *pA, *pB, *pH, *pPB, *pXB;
    cudaGetSymbolAddress(&pA, g_xA);
    cudaGetSymbolAddress(&pB, g_xB);
    cudaGetSymbolAddress(&pH, g_H);
    cudaGetSymbolAddress(&pPB, g_pb);
    cudaGetSymbolAddress(&pXB, g_xb);
    float* gxA = (float*)pA;
    float* gxB = (float*)pB;
    float* gH  = (float*)pH;
    __nv_bfloat16* gpb = (__nv_bfloat16*)pPB;
    __nv_bfloat16* gxb = (__nv_bfloat16*)pXB;

    nb_kernel<<<K_ / 256, 256>>>(prior);
    cvt_bf16_kernel<<<(K_ * F_ / 4) / 256, 256>>>(prior, gpb);

    const float* cur = x0;
    float* bufs[2] = { gxA, gxB };
    for (int l = 0; l < L_; l++) {
        hidden_kernel<<<dim3(B_ / 128, H_ / 128), 256>>>(
            cur, W1 + (size_t)l * HALF_ * H_, b1 + (size_t)l * H_, gH);
        float* xout = (l == L_ - 1) ? out : bufs[l & 1];
        st_kernel<<<B_ / 64, 256>>>(
            cur, gH,
            Ws + (size_t)l * H_ * HALF_, bs + (size_t)l * HALF_,
            Wt + (size_t)l * H_ * HALF_, bt + (size_t)l * HALF_,
            xout, (l == L_ - 1) ? 1 : 0, (l > 0) ? 1 : 0);
        cur = xout;
    }

    cvt_bf16_kernel<<<(B_ * F_ / 4) / 256, 256>>>(out, gxb);

    static int smem_set = 0;
    const int ASMEM = 3 * TILE_BYTES;
    if (!smem_set) {
        cudaFuncSetAttribute(argmin_mma_kernel,
                             cudaFuncAttributeMaxDynamicSharedMemorySize, ASMEM);
        smem_set = 1;
    }
    argmin_mma_kernel<<<dim3(B_ / TM, NSPLIT), 256, ASMEM>>>(gxb, gpb);

    loss_kernel<<<B_ / 8, 256>>>(out, prior);
    if (out_size > B_ * F_)
        final_kernel<<<1, 256>>>(out, out_size);
}

// round 4
// speedup vs baseline: 7.0329x; 1.6491x over previous
#include <cuda_runtime.h>
#include <cuda_bf16.h>
#include <cstdint>

#define B_    8192
#define F_    256
#define HALF_ 128
#define H_    512
#define K_    32768
#define L_    4
#define NSPLIT 16
#define TM 128
#define TN 128
#define TK 256
#define NT (K_ / NSPLIT / TN)   // 16 code tiles per CTA

#define STRB 528                // argmin tile row stride (bytes)
#define TILE_BYTES (128 * STRB) // 67584

#define HSTR 272                // hidden tile row stride: 128 bf16 + 16B pad
#define HTILE (128 * HSTR)      // 34816
#define SSTR 144                // st chunk row stride: 64 bf16 + 16B pad
#define STILE (128 * SSTR)      // 18432

// ---------------- scratch (no allocations allowed) ----------------
__device__ float g_jac[B_];
__device__ float g_nb[K_];
__device__ float g_pmin[B_ * NSPLIT];
__device__ int   g_pidx[B_ * NSPLIT];
__device__ float g_partial[B_ / 8];
__device__ __nv_bfloat16 g_pb[K_ * F_];
__device__ __nv_bfloat16 g_xb[B_ * F_];
__device__ __nv_bfloat16 g_ah0[B_ * HALF_], g_al0[B_ * HALF_];
__device__ __nv_bfloat16 g_ah1[B_ * HALF_], g_al1[B_ * HALF_];
__device__ __nv_bfloat16 g_Hh[B_ * H_], g_Hl[B_ * H_];
__device__ float g_st[B_ * F_];
__device__ float g_y0[B_ * HALF_], g_y1[B_ * HALF_];
__device__ __nv_bfloat16 g_w1h[L_ * H_ * HALF_], g_w1l[L_ * H_ * HALF_];
__device__ __nv_bfloat16 g_wsh[L_ * HALF_ * H_], g_wsl[L_ * HALF_ * H_];
__device__ __nv_bfloat16 g_wth[L_ * HALF_ * H_], g_wtl[L_ * HALF_ * H_];

// ============ PTX helpers (compute_103-safe: sm_80-era tensor ops) ============
__device__ __forceinline__ uint32_t smem_to_u32(const void* p) {
    uint32_t a;
    asm("{ .reg .u64 t; cvta.to.shared.u64 t, %1; cvt.u32.u64 %0, t; }" : "=r"(a) : "l"(p));
    return a;
}
__device__ __forceinline__ void cp16(uint32_t dst, const void* src) {
    asm volatile("cp.async.cg.shared.global [%0], [%1], 16;" :: "r"(dst), "l"(src));
}
#define CP_COMMIT() asm volatile("cp.async.commit_group;" ::: "memory")
#define CP_WAIT0()  asm volatile("cp.async.wait_group 0;" ::: "memory")
#define CP_WAIT1()  asm volatile("cp.async.wait_group 1;" ::: "memory")

__device__ __forceinline__ void ldm_x4(uint32_t* r, uint32_t a) {
    asm volatile("ldmatrix.sync.aligned.m8n8.x4.shared.b16 {%0,%1,%2,%3}, [%4];"
        : "=r"(r[0]), "=r"(r[1]), "=r"(r[2]), "=r"(r[3]) : "r"(a));
}
__device__ __forceinline__ void mma_bf16(float* c, const uint32_t* a, const uint32_t* b) {
    asm volatile(
        "mma.sync.aligned.m16n8k16.row.col.f32.bf16.bf16.f32 "
        "{%0,%1,%2,%3}, {%4,%5,%6,%7}, {%8,%9}, {%0,%1,%2,%3};"
        : "+f"(c[0]), "+f"(c[1]), "+f"(c[2]), "+f"(c[3])
        : "r"(a[0]), "r"(a[1]), "r"(a[2]), "r"(a[3]), "r"(b[0]), "r"(b[1]));
}
__device__ __forceinline__ void bsplit(float v, __nv_bfloat16& h, __nv_bfloat16& l) {
    h = __float2bfloat16_rn(v);
    l = __float2bfloat16_rn(v - __bfloat162float(h));
}
__device__ __forceinline__ uint32_t pack_bf2(float a, float b) {
    __nv_bfloat162 t = __floats2bfloat162_rn(a, b);
    return *(uint32_t*)&t;
}

// ---------------- prep: fp32 -> bf16 (prior) ----------------
__global__ __launch_bounds__(256) void cvt_bf16_kernel(
    const float* __restrict__ src, __nv_bfloat16* __restrict__ dst) {
    int i = blockIdx.x * 256 + threadIdx.x;
    float4 v = ((const float4*)src)[i];
    uint2 u;
    u.x = pack_bf2(v.x, v.y); u.y = pack_bf2(v.z, v.w);
    ((uint2*)dst)[i] = u;
}

// ---------------- prep: ||prior_k||^2 ----------------
__global__ __launch_bounds__(256) void nb_kernel(const float* __restrict__ prior) {
    int k = blockIdx.x * 256 + threadIdx.x;
    const float4* p = (const float4*)(prior + (size_t)k * F_);
    float s = 0.f;
#pragma unroll
    for (int i = 0; i < F_ / 4; i++) {
        float4 v = p[i];
        s = fmaf(v.x, v.x, s); s = fmaf(v.y, v.y, s);
        s = fmaf(v.z, v.z, s); s = fmaf(v.w, v.w, s);
    }
    g_nb[k] = s;
}

// ---------------- prep: transpose + split weights: src [L][R][C] -> dst [L][C][R] ----------------
__global__ __launch_bounds__(256) void wsplit_kernel(
    const float* __restrict__ src, __nv_bfloat16* __restrict__ dh,
    __nv_bfloat16* __restrict__ dl, int R, int C)
{
    int idx = blockIdx.x * 256 + threadIdx.x;
    int l = idx / (R * C); int rem = idx - l * R * C;
    int n = rem / R; int k = rem - n * R;
    float v = src[(size_t)l * R * C + (size_t)k * C + n];
    __nv_bfloat16 h, lo; bsplit(v, h, lo);
    dh[idx] = h; dl[idx] = lo;
}

// ---------------- prep: split xa (cols 0..127 of x0) ----------------
__global__ __launch_bounds__(256) void xsplit_kernel(
    const float* __restrict__ x0, __nv_bfloat16* __restrict__ ah, __nv_bfloat16* __restrict__ al)
{
    int idx = blockIdx.x * 256 + threadIdx.x;   // B_*HALF_
    int r = idx >> 7, c = idx & 127;
    float v = x0[(size_t)r * F_ + c];
    __nv_bfloat16 h, l; bsplit(v, h, l);
    ah[idx] = h; al[idx] = l;
}

// ---------------- hidden: H = relu(xa@W1+b1) via split-bf16 mma ----------------
// grid (64, 4), 256 thr. CTA 128 rows x 128 H-cols, K=128, 3 segments.
__global__ __launch_bounds__(256, 1) void hidden_mma_kernel(
    const __nv_bfloat16* __restrict__ ah, const __nv_bfloat16* __restrict__ al,
    const __nv_bfloat16* __restrict__ wh, const __nv_bfloat16* __restrict__ wl,
    const float* __restrict__ b1,
    __nv_bfloat16* __restrict__ HhOut, __nv_bfloat16* __restrict__ HlOut)
{
    extern __shared__ char sm[];
    uint32_t Ahs = smem_to_u32(sm);
    uint32_t Als = Ahs + HTILE;
    uint32_t Bhs = Ahs + 2 * HTILE;
    uint32_t Bls = Ahs + 3 * HTILE;
    int tid = threadIdx.x, wid = tid >> 5, lane = tid & 31;
    int warp_m = wid & 1, warp_n = wid >> 1;
    int rowbase = blockIdx.x * 128;
    int nbase = blockIdx.y * 128;

#pragma unroll
    for (int i = 0; i < 8; i++) {
        int e = tid + i * 256; int r = e >> 4, c = e & 15;
        cp16(Ahs + r * HSTR + c * 16, (const char*)(ah + (size_t)(rowbase + r) * HALF_) + c * 16);
        cp16(Als + r * HSTR + c * 16, (const char*)(al + (size_t)(rowbase + r) * HALF_) + c * 16);
        cp16(Bhs + r * HSTR + c * 16, (const char*)(wh + (size_t)(nbase + r) * HALF_) + c * 16);
        cp16(Bls + r * HSTR + c * 16, (const char*)(wl + (size_t)(nbase + r) * HALF_) + c * 16);
    }
    CP_COMMIT(); CP_WAIT0(); __syncthreads();

    uint32_t aoff = (uint32_t)((warp_m * 64 + (lane & 15)) * HSTR + ((lane >> 4) * 8) * 2);
    uint32_t boff = (uint32_t)((warp_n * 32 + ((lane >> 4) & 1) * 8 + (lane & 7)) * HSTR
                               + (((lane >> 3) & 1) * 8) * 2);

    float acc[4][4][4];
#pragma unroll
    for (int mi = 0; mi < 4; mi++)
#pragma unroll
        for (int ni = 0; ni < 4; ni++)
#pragma unroll
            for (int q = 0; q < 4; q++) acc[mi][ni][q] = 0.f;

#pragma unroll
    for (int sg = 0; sg < 3; sg++) {
        uint32_t Ab = (sg == 1) ? Als : Ahs;
        uint32_t Bb = (sg == 2) ? Bls : Bhs;
#pragma unroll
        for (int kc = 0; kc < 8; kc++) {
            uint32_t kb = kc * 32;
            uint32_t afrag[4][4], bfrag[4][2];
#pragma unroll
            for (int mi = 0; mi < 4; mi++)
                ldm_x4(afrag[mi], Ab + aoff + kb + (uint32_t)(mi * 16 * HSTR));
#pragma unroll
            for (int pr = 0; pr < 2; pr++) {
                uint32_t r4[4];
                ldm_x4(r4, Bb + boff + kb + (uint32_t)(pr * 16 * HSTR));
                bfrag[pr * 2 + 0][0] = r4[0]; bfrag[pr * 2 + 0][1] = r4[1];
                bfrag[pr * 2 + 1][0] = r4[2]; bfrag[pr * 2 + 1][1] = r4[3];
            }
#pragma unroll
            for (int mi = 0; mi < 4; mi++)
#pragma unroll
                for (int ni = 0; ni < 4; ni++)
                    mma_bf16(acc[mi][ni], afrag[mi], bfrag[ni]);
        }
    }

#pragma unroll
    for (int mi = 0; mi < 4; mi++) {
        int r0 = rowbase + warp_m * 64 + mi * 16 + (lane >> 2);
#pragma unroll
        for (int ni = 0; ni < 4; ni++) {
            int c0 = nbase + warp_n * 32 + ni * 8 + (lane & 3) * 2;
            float bb0 = b1[c0], bb1 = b1[c0 + 1];
#pragma unroll
            for (int h = 0; h < 2; h++) {
                int r = r0 + h * 8;
                float v0 = acc[mi][ni][h * 2 + 0] + bb0; v0 = v0 > 0.f ? v0 : 0.f;
                float v1 = acc[mi][ni][h * 2 + 1] + bb1; v1 = v1 > 0.f ? v1 : 0.f;
                __nv_bfloat16 h0, h1, l0, l1;
                bsplit(v0, h0, l0); bsplit(v1, h1, l1);
                __nv_bfloat162 hv = __halves2bfloat162(h0, h1);
                __nv_bfloat162 lv = __halves2bfloat162(l0, l1);
                *(__nv_bfloat162*)(HhOut + (size_t)r * H_ + c0) = hv;
                *(__nv_bfloat162*)(HlOut + (size_t)r * H_ + c0) = lv;
            }
        }
    }
}

// ---------------- st: s_raw|t = H@Ws / H@Wt via split-bf16 mma ----------------
// grid (64, 2): y=0 -> s (Ws), y=1 -> t (Wt). CTA 128 rows x 128 cols, K=512 streamed.
__device__ __forceinline__ void st_load_chunk(
    uint32_t Adst, uint32_t Bdst,
    const __nv_bfloat16* As, const __nv_bfloat16* Bs,
    int rowbase, int k0, int tid)
{
#pragma unroll
    for (int i = 0; i < 4; i++) {
        int e = tid + i * 256; int r = e >> 3, c = e & 7;
        cp16(Adst + r * SSTR + c * 16, (const char*)(As + (size_t)(rowbase + r) * H_ + k0) + c * 16);
        cp16(Bdst + r * SSTR + c * 16, (const char*)(Bs + (size_t)r * H_ + k0) + c * 16);
    }
}

__global__ __launch_bounds__(256, 1) void st_mma_kernel(
    const __nv_bfloat16* __restrict__ Hh, const __nv_bfloat16* __restrict__ Hl,
    const __nv_bfloat16* __restrict__ wsh, const __nv_bfloat16* __restrict__ wsl,
    const __nv_bfloat16* __restrict__ wth, const __nv_bfloat16* __restrict__ wtl,
    const float* __restrict__ bs, const float* __restrict__ bt,
    float* __restrict__ stout)
{
    extern __shared__ char sm[];
    uint32_t base = smem_to_u32(sm);
    uint32_t Ab0 = base,             Ab1 = base + STILE;
    uint32_t Bb0 = base + 2 * STILE, Bb1 = base + 3 * STILE;
    int tid = threadIdx.x, wid = tid >> 5, lane = tid & 31;
    int warp_m = wid & 1, warp_n = wid >> 1;
    int rowbase = blockIdx.x * 128;
    int ntile = blockIdx.y;
    const __nv_bfloat16* bwh = ntile ? wth : wsh;
    const __nv_bfloat16* bwl = ntile ? wtl : wsl;
    const float* bias = ntile ? bt : bs;

    st_load_chunk(Ab0, Bb0, Hh, bwh, rowbase, 0, tid);
    CP_COMMIT();

    uint32_t aoff = (uint32_t)((warp_m * 64 + (lane & 15)) * SSTR + ((lane >> 4) * 8) * 2);
    uint32_t boff = (uint32_t)((warp_n * 32 + ((lane >> 4) & 1) * 8 + (lane & 7)) * SSTR
                               + (((lane >> 3) & 1) * 8) * 2);

    float acc[4][4][4];
#pragma unroll
    for (int mi = 0; mi < 4; mi++)
#pragma unroll
        for (int ni = 0; ni < 4; ni++)
#pragma unroll
            for (int q = 0; q < 4; q++) acc[mi][ni][q] = 0.f;

    for (int idx = 0; idx < 24; idx++) {
        int cur = idx & 1;
        if (idx + 1 < 24) {
            int sg = (idx + 1) >> 3, k0 = ((idx + 1) & 7) * 64;
            const __nv_bfloat16* As = (sg == 1) ? Hl : Hh;
            const __nv_bfloat16* Bs = (sg == 2) ? bwl : bwh;
            st_load_chunk(cur ? Ab0 : Ab1, cur ? Bb0 : Bb1, As, Bs, rowbase, k0, tid);
            CP_COMMIT();
            CP_WAIT1();
        } else {
            CP_WAIT0();
        }
        __syncthreads();
        uint32_t Abc = cur ? Ab1 : Ab0;
        uint32_t Bbc = cur ? Bb1 : Bb0;
#pragma unroll
        for (int kc = 0; kc < 4; kc++) {
            uint32_t kb = kc * 32;
            uint32_t afrag[4][4], bfrag[4][2];
#pragma unroll
            for (int mi = 0; mi < 4; mi++)
                ldm_x4(afrag[mi], Abc + aoff + kb + (uint32_t)(mi * 16 * SSTR));
#pragma unroll
            for (int pr = 0; pr < 2; pr++) {
                uint32_t r4[4];
                ldm_x4(r4, Bbc + boff + kb + (uint32_t)(pr * 16 * SSTR));
                bfrag[pr * 2 + 0][0] = r4[0]; bfrag[pr * 2 + 0][1] = r4[1];
                bfrag[pr * 2 + 1][0] = r4[2]; bfrag[pr * 2 + 1][1] = r4[3];
            }
#pragma unroll
            for (int mi = 0; mi < 4; mi++)
#pragma unroll
                for (int ni = 0; ni < 4; ni++)
                    mma_bf16(acc[mi][ni], afrag[mi], bfrag[ni]);
        }
        __syncthreads();
    }

#pragma unroll
    for (int mi = 0; mi < 4; mi++) {
        int r0 = rowbase + warp_m * 64 + mi * 16 + (lane >> 2);
#pragma unroll
        for (int ni = 0; ni < 4; ni++) {
            int c0 = warp_n * 32 + ni * 8 + (lane & 3) * 2;
            float b0 = bias[c0], b1v = bias[c0 + 1];
#pragma unroll
            for (int h = 0; h < 2; h++) {
                int r = r0 + h * 8;
                float2 v;
                v.x = acc[mi][ni][h * 2 + 0] + b0;
                v.y = acc[mi][ni][h * 2 + 1] + b1v;
                *(float2*)(stout + (size_t)r * F_ + ntile * HALF_ + c0) = v;
            }
        }
    }
}

// ---------------- coupling epilogue ----------------
// grid 1024 x 256 (warp per row). y = xb*exp(s)+t; jac row-sum; emit next xa splits.
__global__ __launch_bounds__(256) void couple_kernel(
    const float* __restrict__ stin,
    const float* __restrict__ xa, int sxa,
    const float* __restrict__ xb, int sxb,
    float* __restrict__ yb,
    __nv_bfloat16* __restrict__ yh, __nv_bfloat16* __restrict__ yl,
    float* __restrict__ out, __nv_bfloat16* __restrict__ outb,
    int is_last, int accum)
{
    int warp = threadIdx.x >> 5, lane = threadIdx.x & 31;
    int r = blockIdx.x * 8 + warp;
    float4 s4 = ((const float4*)(stin + (size_t)r * F_))[lane];
    float4 t4 = ((const float4*)(stin + (size_t)r * F_ + HALF_))[lane];
    float4 xb4 = ((const float4*)(xb + (size_t)r * sxb))[lane];
    if (!is_last) {
        s4.x = tanhf(s4.x); s4.y = tanhf(s4.y);
        s4.z = tanhf(s4.z); s4.w = tanhf(s4.w);
    }
    float4 y;
    y.x = fmaf(xb4.x, expf(s4.x), t4.x);
    y.y = fmaf(xb4.y, expf(s4.y), t4.y);
    y.z = fmaf(xb4.z, expf(s4.z), t4.z);
    y.w = fmaf(xb4.w, expf(s4.w), t4.w);

    float js = s4.x + s4.y + s4.z + s4.w;
#pragma unroll
    for (int off = 16; off; off >>= 1) js += __shfl_down_sync(0xffffffff, js, off);
    if (lane == 0) g_jac[r] = accum ? g_jac[r] + js : js;

    if (!is_last) {
        ((float4*)(yb + (size_t)r * HALF_))[lane] = y;
        __nv_bfloat16 h0, h1, h2, h3, l0, l1, l2, l3;
        bsplit(y.x, h0, l0); bsplit(y.y, h1, l1);
        bsplit(y.z, h2, l2); bsplit(y.w, h3, l3);
        uint2 hv, lv;
        __nv_bfloat162 p01 = __halves2bfloat162(h0, h1), p23 = __halves2bfloat162(h2, h3);
        __nv_bfloat162 q01 = __halves2bfloat162(l0, l1), q23 = __halves2bfloat162(l2, l3);
        hv.x = *(uint32_t*)&p01; hv.y = *(uint32_t*)&p23;
        lv.x = *(uint32_t*)&q01; lv.y = *(uint32_t*)&q23;
        ((uint2*)(yh + (size_t)r * HALF_))[lane] = hv;
        ((uint2*)(yl + (size_t)r * HALF_))[lane] = lv;
    } else {
        float4 xa4 = ((const float4*)(xa + (size_t)r * sxa))[lane];
        ((float4*)(out + (size_t)r * F_))[lane] = y;
        ((float4*)(out + (size_t)r * F_ + HALF_))[lane] = xa4;
        uint2 u;
        u.x = pack_bf2(y.x, y.y); u.y = pack_bf2(y.z, y.w);
        ((uint2*)(outb + (size_t)r * F_))[lane] = u;
        u.x = pack_bf2(xa4.x, xa4.y); u.y = pack_bf2(xa4.z, xa4.w);
        ((uint2*)(outb + (size_t)r * F_ + HALF_))[lane] = u;
    }
}

// ---------------- mma.sync bf16 distance GEMM + fused argmin (unchanged) ----------------
__global__ __launch_bounds__(256, 1) void argmin_mma_kernel(
    const __nv_bfloat16* __restrict__ xb, const __nv_bfloat16* __restrict__ pb)
{
    extern __shared__ char dsmem[];
    __shared__ __align__(16) float s_nb[2][TN];
    __shared__ float redv[TM][4];
    __shared__ int   redi[TM][4];

    uint32_t Abase = smem_to_u32(dsmem);
    uint32_t Bbase[2] = { Abase + TILE_BYTES, Abase + 2 * TILE_BYTES };

    int tid = threadIdx.x;
    int wid = tid >> 5, lane = tid & 31;
    int warp_m = wid & 1;
    int warp_n = wid >> 1;
    int rowbase = blockIdx.x * TM;
    int split = blockIdx.y;
    int code0 = split * (K_ / NSPLIT);

#pragma unroll
    for (int i = 0; i < 16; i++) {
        int e = tid + i * 256;
        int r = e >> 5, c = e & 31;
        cp16(Abase + r * STRB + c * 16,
             (const char*)(xb + (size_t)(rowbase + r) * TK) + c * 16);
    }
#pragma unroll
    for (int i = 0; i < 16; i++) {
        int e = tid + i * 256;
        int r = e >> 5, c = e & 31;
        cp16(Bbase[0] + r * STRB + c * 16,
             (const char*)(pb + (size_t)(code0 + r) * TK) + c * 16);
    }
    if (tid < TN) s_nb[0][tid] = g_nb[code0 + tid];
    CP_COMMIT();
    CP_WAIT0();
    __syncthreads();

    uint32_t aoff = (uint32_t)((warp_m * 64 + (lane & 15)) * STRB + ((lane >> 4) * 8) * 2);
    uint32_t boff = (uint32_t)((warp_n * 32 + ((lane >> 4) & 1) * 8 + (lane & 7)) * STRB
                               + (((lane >> 3) & 1) * 8) * 2);

    float minv[8];
    int   mini[8];
#pragma unroll
    for (int i = 0; i < 8; i++) { minv[i] = 3.4e38f; mini[i] = 0; }

    for (int t = 0; t < NT; t++) {
        int cb = t & 1;
        if (t + 1 < NT) {
            int nb_ = (t + 1) & 1;
            int codeN = code0 + (t + 1) * TN;
#pragma unroll
            for (int i = 0; i < 16; i++) {
                int e = tid + i * 256;
                int r = e >> 5, c = e & 31;
                cp16(Bbase[nb_] + r * STRB + c * 16,
                     (const char*)(pb + (size_t)(codeN + r) * TK) + c * 16);
            }
            CP_COMMIT();
            if (tid < TN) s_nb[nb_][tid] = g_nb[codeN + tid];
        }

        float acc[4][4][4];
#pragma unroll
        for (int mi = 0; mi < 4; mi++)
#pragma unroll
            for (int ni = 0; ni < 4; ni++)
#pragma unroll
                for (int q = 0; q < 4; q++) acc[mi][ni][q] = 0.f;

#pragma unroll
        for (int kc = 0; kc < 16; kc++) {
            uint32_t kb = kc * 32;
            uint32_t afrag[4][4], bfrag[4][2];
#pragma unroll
            for (int mi = 0; mi < 4; mi++)
                ldm_x4(afrag[mi], Abase + aoff + kb + (uint32_t)(mi * 16 * STRB));
#pragma unroll
            for (int pr = 0; pr < 2; pr++) {
                uint32_t r4[4];
                ldm_x4(r4, Bbase[cb] + boff + kb + (uint32_t)(pr * 16 * STRB));
                bfrag[pr * 2 + 0][0] = r4[0]; bfrag[pr * 2 + 0][1] = r4[1];
                bfrag[pr * 2 + 1][0] = r4[2]; bfrag[pr * 2 + 1][1] = r4[3];
            }
#pragma unroll
            for (int mi = 0; mi < 4; mi++)
#pragma unroll
                for (int ni = 0; ni < 4; ni++)
                    mma_bf16(acc[mi][ni], afrag[mi], bfrag[ni]);
        }

        int ctile = code0 + t * TN;
#pragma unroll
        for (int mi = 0; mi < 4; mi++)
#pragma unroll
            for (int ni = 0; ni < 4; ni++)
#pragma unroll
                for (int q = 0; q < 4; q++) {
                    int cl = warp_n * 32 + ni * 8 + (lane & 3) * 2 + (q & 1);
                    float v = fmaf(-2.f, acc[mi][ni][q], s_nb[cb][cl]);
                    int ridx = mi * 2 + (q >> 1);
                    if (v < minv[ridx]) { minv[ridx] = v; mini[ridx] = ctile + cl; }
                }

        CP_WAIT0();
        __syncthreads();
    }

#pragma unroll
    for (int ridx = 0; ridx < 8; ridx++) {
        float v = minv[ridx]; int ii = mini[ridx];
#pragma unroll
        for (int off = 1; off <= 2; off <<= 1) {
            float ov = __shfl_xor_sync(0xffffffff, v, off);
            int   oi = __shfl_xor_sync(0xffffffff, ii, off);
            if (ov < v || (ov == v && oi < ii)) { v = ov; ii = oi; }
        }
        if ((lane & 3) == 0) {
            int row = warp_m * 64 + (ridx >> 1) * 16 + (ridx & 1) * 8 + (lane >> 2);
            redv[row][warp_n] = v;
            redi[row][warp_n] = ii;
        }
    }
    __syncthreads();
    if (tid < TM) {
        float bv = redv[tid][0]; int bi = redi[tid][0];
#pragma unroll
        for (int q = 1; q < 4; q++) {
            float v = redv[tid][q]; int ii = redi[tid][q];
            if (v < bv || (v == bv && ii < bi)) { bv = v; bi = ii; }
        }
        g_pmin[(size_t)(rowbase + tid) * NSPLIT + split] = bv;
        g_pidx[(size_t)(rowbase + tid) * NSPLIT + split] = bi;
    }
}

// ---------------- per-row loss partials (deterministic) ----------------
__global__ __launch_bounds__(256) void loss_kernel(
    const float* __restrict__ x, const float* __restrict__ prior)
{
    int warp = threadIdx.x >> 5, lane = threadIdx.x & 31;
    int r = blockIdx.x * 8 + warp;
    float v = 3.4e38f; int idx = 0x7fffffff;
    if (lane < NSPLIT) { v = g_pmin[(size_t)r * NSPLIT + lane]; idx = g_pidx[(size_t)r * NSPLIT + lane]; }
#pragma unroll
    for (int off = 8; off; off >>= 1) {
        float ov = __shfl_down_sync(0xffffffff, v, off);
        int   oi = __shfl_down_sync(0xffffffff, idx, off);
        if (ov < v || (ov == v && oi < idx)) { v = ov; idx = oi; }
    }
    idx = __shfl_sync(0xffffffff, idx, 0);
    float ss = 0.f;
#pragma unroll
    for (int f = lane; f < F_; f += 32) {
        float d = x[(size_t)r * F_ + f] - prior[(size_t)idx * F_ + f];
        ss = fmaf(d, d, ss);
    }
#pragma unroll
    for (int off = 16; off; off >>= 1) ss += __shfl_down_sync(0xffffffff, ss, off);
    __shared__ float part[8];
    if (lane == 0) part[warp] = fmaf(0.625f, ss, -g_jac[r]);
    __syncthreads();
    if (threadIdx.x == 0) {
        float s = 0.f;
#pragma unroll
        for (int i = 0; i < 8; i++) s += part[i];
        g_partial[blockIdx.x] = s;
    }
}

__global__ __launch_bounds__(256) void final_kernel(float* out, int out_size) {
    __shared__ float sm[256];
    int tid = threadIdx.x;
    float s = 0.f;
    for (int i = tid; i < B_ / 8; i += 256) s += g_partial[i];
    sm[tid] = s;
    __syncthreads();
    for (int st = 128; st; st >>= 1) { if (tid < st) sm[tid] += sm[tid + st]; __syncthreads(); }
    float loss = sm[0] / (float)B_;
    for (int i = B_ * F_ + tid; i < out_size; i += 256) out[i] = loss;
}

// ---------------- launch ----------------
static void* sym(const void* s) { void* p; cudaGetSymbolAddress(&p, s); return p; }

extern "C" void kernel_launch(void* const* d_in, const int* in_sizes, int n_in,
                              void* d_out, int out_size) {
    const float* x0    = (const float*)d_in[0];
    const float* W1    = (const float*)d_in[1];
    const float* b1    = (const float*)d_in[2];
    const float* Ws    = (const float*)d_in[3];
    const float* bs    = (const float*)d_in[4];
    const float* Wt    = (const float*)d_in[5];
    const float* bt    = (const float*)d_in[6];
    const float* prior = (const float*)d_in[7];
    float* out = (float*)d_out;

    __nv_bfloat16* gpb  = (__nv_bfloat16*)sym(g_pb);
    __nv_bfloat16* gxb  = (__nv_bfloat16*)sym(g_xb);
    __nv_bfloat16* ahB[2] = { (__nv_bfloat16*)sym(g_ah0), (__nv_bfloat16*)sym(g_ah1) };
    __nv_bfloat16* alB[2] = { (__nv_bfloat16*)sym(g_al0), (__nv_bfloat16*)sym(g_al1) };
    __nv_bfloat16* gHh  = (__nv_bfloat16*)sym(g_Hh);
    __nv_bfloat16* gHl  = (__nv_bfloat16*)sym(g_Hl);
    float* gst = (float*)sym(g_st);
    float* yB[2] = { (float*)sym(g_y0), (float*)sym(g_y1) };
    __nv_bfloat16* w1h = (__nv_bfloat16*)sym(g_w1h);
    __nv_bfloat16* w1l = (__nv_bfloat16*)sym(g_w1l);
    __nv_bfloat16* wsh = (__nv_bfloat16*)sym(g_wsh);
    __nv_bfloat16* wsl = (__nv_bfloat16*)sym(g_wsl);
    __nv_bfloat16* wth = (__nv_bfloat16*)sym(g_wth);
    __nv_bfloat16* wtl = (__nv_bfloat16*)sym(g_wtl);

    static int smem_set = 0;
    const int ASMEM = 3 * TILE_BYTES;     // 202752
    const int HSMEM = 4 * HTILE;          // 139264
    const int SSMEM = 4 * STILE;          // 73728
    if (!smem_set) {
        cudaFuncSetAttribute(argmin_mma_kernel, cudaFuncAttributeMaxDynamicSharedMemorySize, ASMEM);
        cudaFuncSetAttribute(hidden_mma_kernel, cudaFuncAttributeMaxDynamicSharedMemorySize, HSMEM);
        cudaFuncSetAttribute(st_mma_kernel, cudaFuncAttributeMaxDynamicSharedMemorySize, SSMEM);
        smem_set = 1;
    }

    // prep
    nb_kernel<<<K_ / 256, 256>>>(prior);
    cvt_bf16_kernel<<<(K_ * F_ / 4) / 256, 256>>>(prior, gpb);
    wsplit_kernel<<<(L_ * HALF_ * H_) / 256, 256>>>(W1, w1h, w1l, HALF_, H_);
    wsplit_kernel<<<(L_ * HALF_ * H_) / 256, 256>>>(Ws, wsh, wsl, H_, HALF_);
    wsplit_kernel<<<(L_ * HALF_ * H_) / 256, 256>>>(Wt, wth, wtl, H_, HALF_);
    xsplit_kernel<<<(B_ * HALF_) / 256, 256>>>(x0, ahB[0], alB[0]);

    // flow
    const float* XA = x0;        int sxa = F_;
    const float* XB = x0 + HALF_; int sxb = F_;
    for (int l = 0; l < L_; l++) {
        hidden_mma_kernel<<<dim3(B_ / 128, H_ / 128), 256, HSMEM>>>(
            ahB[l & 1], alB[l & 1],
            w1h + (size_t)l * H_ * HALF_, w1l + (size_t)l * H_ * HALF_,
            b1 + (size_t)l * H_, gHh, gHl);
        st_mma_kernel<<<dim3(B_ / 128, 2), 256, SSMEM>>>(
            gHh, gHl,
            wsh + (size_t)l * HALF_ * H_, wsl + (size_t)l * HALF_ * H_,
            wth + (size_t)l * HALF_ * H_, wtl + (size_t)l * HALF_ * H_,
            bs + (size_t)l * HALF_, bt + (size_t)l * HALF_, gst);
        int last = (l == L_ - 1);
        couple_kernel<<<B_ / 8, 256>>>(
            gst, XA, sxa, XB, sxb,
            yB[l & 1], ahB[(l + 1) & 1], alB[(l + 1) & 1],
            out, gxb, last, l > 0);
        XB = XA; sxb = sxa;
        XA = yB[l & 1]; sxa = HALF_;
    }

    // VQ argmin + loss
    argmin_mma_kernel<<<dim3(B_ / TM, NSPLIT), 256, ASMEM>>>(gxb, gpb);
    loss_kernel<<<B_ / 8, 256>>>(out, prior);
    if (out_size > B_ * F_)
        final_kernel<<<1, 256>>>(out, out_size);
}